// round 1
// baseline (speedup 1.0000x reference)
#include <cuda_runtime.h>
#include <math.h>

#define N_ROWS 65536
#define C      1000
#define C4     250     // float4 chunks per row
#define BLK    256

// Per-row partial results: sum(P*x) - sum(P)*lse  (scratch, allowed as device global)
__device__ float g_partial[N_ROWS];

__device__ __forceinline__ float warp_max(float v) {
    #pragma unroll
    for (int o = 16; o; o >>= 1) v = fmaxf(v, __shfl_xor_sync(0xffffffffu, v, o));
    return v;
}
__device__ __forceinline__ float warp_sum(float v) {
    #pragma unroll
    for (int o = 16; o; o >>= 1) v += __shfl_xor_sync(0xffffffffu, v, o);
    return v;
}

__global__ __launch_bounds__(BLK) void ebem_row_kernel(
    const float* __restrict__ x, const float* __restrict__ P)
{
    const int row = blockIdx.x;
    const int t   = threadIdx.x;
    const int wid = t >> 5;
    const int lane = t & 31;

    // Row bases: row*4000 bytes, 16B-aligned -> float4 OK.
    const float4* __restrict__ x4 = reinterpret_cast<const float4*>(x + (size_t)row * C);
    const float4* __restrict__ p4 = reinterpret_cast<const float4*>(P + (size_t)row * C);

    float4 xv = make_float4(-1e30f, -1e30f, -1e30f, -1e30f);
    float4 pv = make_float4(0.f, 0.f, 0.f, 0.f);
    if (t < C4) {
        xv = x4[t];
        pv = p4[t];
    }

    // ---- block max ----
    __shared__ float smax[8];
    __shared__ float sbcast;
    float m = fmaxf(fmaxf(xv.x, xv.y), fmaxf(xv.z, xv.w));
    m = warp_max(m);
    if (lane == 0) smax[wid] = m;
    __syncthreads();
    if (wid == 0) {
        float v = (lane < 8) ? smax[lane] : -1e30f;
        v = warp_max(v);
        if (lane == 0) sbcast = v;
    }
    __syncthreads();
    m = sbcast;

    // ---- per-thread sums (inactive threads: exp(-1e30-m)=0, pv=0) ----
    float se  = __expf(xv.x - m) + __expf(xv.y - m) + __expf(xv.z - m) + __expf(xv.w - m);
    float spx = pv.x * xv.x + pv.y * xv.y + pv.z * xv.z + pv.w * xv.w;
    float sp  = pv.x + pv.y + pv.z + pv.w;

    // ---- block sum of 3 values ----
    __shared__ float s3[3][8];
    se  = warp_sum(se);
    spx = warp_sum(spx);
    sp  = warp_sum(sp);
    if (lane == 0) { s3[0][wid] = se; s3[1][wid] = spx; s3[2][wid] = sp; }
    __syncthreads();
    if (wid == 0) {
        float a = (lane < 8) ? s3[0][lane] : 0.f;
        float b = (lane < 8) ? s3[1][lane] : 0.f;
        float c = (lane < 8) ? s3[2][lane] : 0.f;
        a = warp_sum(a); b = warp_sum(b); c = warp_sum(c);
        if (lane == 0) {
            float lse = m + logf(a);
            g_partial[row] = b - c * lse;   // sum(P*x) - sum(P)*lse
        }
    }
}

__global__ __launch_bounds__(1024) void ebem_reduce_kernel(float* __restrict__ out)
{
    double acc = 0.0;
    for (int i = threadIdx.x; i < N_ROWS; i += 1024)
        acc += (double)g_partial[i];

    #pragma unroll
    for (int o = 16; o; o >>= 1) acc += __shfl_xor_sync(0xffffffffu, acc, o);

    __shared__ double sh[32];
    const int wid = threadIdx.x >> 5, lane = threadIdx.x & 31;
    if (lane == 0) sh[wid] = acc;
    __syncthreads();
    if (wid == 0) {
        acc = (lane < 32) ? sh[lane] : 0.0;
        #pragma unroll
        for (int o = 16; o; o >>= 1) acc += __shfl_xor_sync(0xffffffffu, acc, o);
        if (lane == 0) out[0] = (float)(-acc / (double)N_ROWS);
    }
}

extern "C" void kernel_launch(void* const* d_in, const int* in_sizes, int n_in,
                              void* d_out, int out_size)
{
    const float* x = (const float*)d_in[0];
    const float* P = (const float*)d_in[1];
    float* out = (float*)d_out;

    ebem_row_kernel<<<N_ROWS, BLK>>>(x, P);
    ebem_reduce_kernel<<<1, 1024>>>(out);
}

// round 4
// speedup vs baseline: 1.3092x; 1.3092x over previous
#include <cuda_runtime.h>
#include <math.h>

#define N_ROWS 65536
#define C      1000
#define C4     250          // float4 chunks per row
#define BLK    128          // 4 warps -> 4 rows per CTA
#define ROWS_PER_BLK (BLK / 32)

// Per-row partial results: sum(P*x) - sum(P)*lse
__device__ float g_partial[N_ROWS];

__device__ __forceinline__ float warp_max(float v) {
    #pragma unroll
    for (int o = 16; o; o >>= 1) v = fmaxf(v, __shfl_xor_sync(0xffffffffu, v, o));
    return v;
}
__device__ __forceinline__ float warp_sum(float v) {
    #pragma unroll
    for (int o = 16; o; o >>= 1) v += __shfl_xor_sync(0xffffffffu, v, o);
    return v;
}
__device__ __forceinline__ double warp_sum_d(double v) {
    #pragma unroll
    for (int o = 16; o; o >>= 1) v += __shfl_xor_sync(0xffffffffu, v, o);
    return v;
}

// One warp per row: no block barriers, 16 front-batched LDG.128 per thread.
__global__ __launch_bounds__(BLK) void ebem_row_kernel(
    const float* __restrict__ x, const float* __restrict__ P)
{
    const int warp_in_blk = threadIdx.x >> 5;
    const int lane        = threadIdx.x & 31;
    const int row         = blockIdx.x * ROWS_PER_BLK + warp_in_blk;

    const float4* __restrict__ x4 = reinterpret_cast<const float4*>(x + (size_t)row * C);
    const float4* __restrict__ p4 = reinterpret_cast<const float4*>(P + (size_t)row * C);

    float4 xv[8], pv[8];
    #pragma unroll
    for (int i = 0; i < 8; i++) {
        const int idx = lane + 32 * i;
        if (idx < C4) {
            xv[i] = x4[idx];
            pv[i] = p4[idx];
        } else {
            xv[i] = make_float4(-1e30f, -1e30f, -1e30f, -1e30f);
            pv[i] = make_float4(0.f, 0.f, 0.f, 0.f);
        }
    }

    // row max (shuffle-only)
    float m = -1e30f;
    #pragma unroll
    for (int i = 0; i < 8; i++)
        m = fmaxf(m, fmaxf(fmaxf(xv[i].x, xv[i].y), fmaxf(xv[i].z, xv[i].w)));
    m = warp_max(m);

    // per-thread sums; padded lanes: exp(-1e30-m)=0, pv=0
    float se = 0.f, spx = 0.f, sp = 0.f;
    #pragma unroll
    for (int i = 0; i < 8; i++) {
        se  += __expf(xv[i].x - m) + __expf(xv[i].y - m)
             + __expf(xv[i].z - m) + __expf(xv[i].w - m);
        spx += pv[i].x * xv[i].x + pv[i].y * xv[i].y
             + pv[i].z * xv[i].z + pv[i].w * xv[i].w;
        sp  += pv[i].x + pv[i].y + pv[i].z + pv[i].w;
    }

    se  = warp_sum(se);
    spx = warp_sum(spx);
    sp  = warp_sum(sp);

    if (lane == 0) {
        float lse = m + logf(se);
        g_partial[row] = spx - sp * lse;
    }
}

// Single-block final reduce: float4 loads (high MLP), double accumulation.
__global__ __launch_bounds__(1024) void ebem_reduce_kernel(float* __restrict__ out)
{
    const float4* __restrict__ p4 = reinterpret_cast<const float4*>(g_partial);
    const int NV = N_ROWS / 4;   // 16384 -> 16 iters per thread at 1024 threads

    double acc = 0.0;
    for (int i = threadIdx.x; i < NV; i += 1024) {
        float4 v = p4[i];
        acc += (double)v.x + (double)v.y + (double)v.z + (double)v.w;
    }

    acc = warp_sum_d(acc);

    __shared__ double sh[32];
    const int wid = threadIdx.x >> 5, lane = threadIdx.x & 31;
    if (lane == 0) sh[wid] = acc;
    __syncthreads();
    if (wid == 0) {
        acc = sh[lane];
        acc = warp_sum_d(acc);
        if (lane == 0) out[0] = (float)(-acc / (double)N_ROWS);
    }
}

extern "C" void kernel_launch(void* const* d_in, const int* in_sizes, int n_in,
                              void* d_out, int out_size)
{
    const float* x = (const float*)d_in[0];
    const float* P = (const float*)d_in[1];
    float* out = (float*)d_out;

    ebem_row_kernel<<<N_ROWS / ROWS_PER_BLK, BLK>>>(x, P);
    ebem_reduce_kernel<<<1, 1024>>>(out);
}

// round 5
// speedup vs baseline: 1.3509x; 1.0319x over previous
#include <cuda_runtime.h>
#include <math.h>

#define N_ROWS 65536
#define C      1000
#define C4     250          // float4 chunks per row
#define BLK    128          // 4 warps -> 4 rows per CTA
#define ROWS_PER_BLK (BLK / 32)
#define N_BUCKETS 256
#define FP_SCALE  67108864.0   // 2^26 fixed-point scale

// Fixed-point accumulation buckets: integer atomics are exactly commutative,
// so the result is bit-identical on every replay.
__device__ long long g_buckets[N_BUCKETS];

__device__ __forceinline__ float warp_max(float v) {
    #pragma unroll
    for (int o = 16; o; o >>= 1) v = fmaxf(v, __shfl_xor_sync(0xffffffffu, v, o));
    return v;
}
__device__ __forceinline__ float warp_sum(float v) {
    #pragma unroll
    for (int o = 16; o; o >>= 1) v += __shfl_xor_sync(0xffffffffu, v, o);
    return v;
}

__global__ void ebem_init_kernel()
{
    g_buckets[threadIdx.x] = 0LL;
}

// One warp per row: no barriers until the final 4-value CTA reduce.
__global__ __launch_bounds__(BLK) void ebem_row_kernel(
    const float* __restrict__ x, const float* __restrict__ P)
{
    const int warp_in_blk = threadIdx.x >> 5;
    const int lane        = threadIdx.x & 31;
    const int row         = blockIdx.x * ROWS_PER_BLK + warp_in_blk;

    const float4* __restrict__ x4 = reinterpret_cast<const float4*>(x + (size_t)row * C);
    const float4* __restrict__ p4 = reinterpret_cast<const float4*>(P + (size_t)row * C);

    float4 xv[8], pv[8];
    #pragma unroll
    for (int i = 0; i < 8; i++) {
        const int idx = lane + 32 * i;
        if (idx < C4) {
            xv[i] = x4[idx];
            pv[i] = p4[idx];
        } else {
            xv[i] = make_float4(-1e30f, -1e30f, -1e30f, -1e30f);
            pv[i] = make_float4(0.f, 0.f, 0.f, 0.f);
        }
    }

    // row max (shuffle-only)
    float m = -1e30f;
    #pragma unroll
    for (int i = 0; i < 8; i++)
        m = fmaxf(m, fmaxf(fmaxf(xv[i].x, xv[i].y), fmaxf(xv[i].z, xv[i].w)));
    m = warp_max(m);

    // per-thread sums; padded lanes: exp(-1e30-m)=0, pv=0
    float se = 0.f, spx = 0.f, sp = 0.f;
    #pragma unroll
    for (int i = 0; i < 8; i++) {
        se  += __expf(xv[i].x - m) + __expf(xv[i].y - m)
             + __expf(xv[i].z - m) + __expf(xv[i].w - m);
        spx += pv[i].x * xv[i].x + pv[i].y * xv[i].y
             + pv[i].z * xv[i].z + pv[i].w * xv[i].w;
        sp  += pv[i].x + pv[i].y + pv[i].z + pv[i].w;
    }

    se  = warp_sum(se);
    spx = warp_sum(spx);
    sp  = warp_sum(sp);

    // CTA-level: 4 warp partials -> 1 fixed-point atomic
    __shared__ float s_part[ROWS_PER_BLK];
    if (lane == 0) {
        float lse = m + logf(se);
        s_part[warp_in_blk] = spx - sp * lse;
    }
    __syncthreads();
    if (threadIdx.x == 0) {
        double acc = (double)s_part[0] + (double)s_part[1]
                   + (double)s_part[2] + (double)s_part[3];
        long long q = __double2ll_rn(acc * FP_SCALE);
        atomicAdd(reinterpret_cast<unsigned long long*>(
                      &g_buckets[blockIdx.x & (N_BUCKETS - 1)]),
                  (unsigned long long)q);
    }
}

// Exact integer sum of 256 buckets -> final float loss.
__global__ __launch_bounds__(N_BUCKETS) void ebem_final_kernel(float* __restrict__ out)
{
    long long v = g_buckets[threadIdx.x];

    // warp-level integer sum
    #pragma unroll
    for (int o = 16; o; o >>= 1)
        v += __shfl_xor_sync(0xffffffffu, v, o);

    __shared__ long long sh[8];
    const int wid = threadIdx.x >> 5, lane = threadIdx.x & 31;
    if (lane == 0) sh[wid] = v;
    __syncthreads();
    if (wid == 0) {
        long long t = (lane < 8) ? sh[lane] : 0LL;
        #pragma unroll
        for (int o = 4; o; o >>= 1)
            t += __shfl_xor_sync(0xffffffffu, t, o);
        if (lane == 0)
            out[0] = (float)(-((double)t / FP_SCALE) / (double)N_ROWS);
    }
}

extern "C" void kernel_launch(void* const* d_in, const int* in_sizes, int n_in,
                              void* d_out, int out_size)
{
    const float* x = (const float*)d_in[0];
    const float* P = (const float*)d_in[1];
    float* out = (float*)d_out;

    ebem_init_kernel<<<1, N_BUCKETS>>>();
    ebem_row_kernel<<<N_ROWS / ROWS_PER_BLK, BLK>>>(x, P);
    ebem_final_kernel<<<1, N_BUCKETS>>>(out);
}

// round 6
// speedup vs baseline: 1.4082x; 1.0424x over previous
#include <cuda_runtime.h>
#include <math.h>

#define N_ROWS 65536
#define C      1000
#define C4     250          // float4 chunks per row
#define BLK    128          // 4 warps -> 4 rows per CTA
#define ROWS_PER_BLK (BLK / 32)
#define GRID   (N_ROWS / ROWS_PER_BLK)   // 16384
#define N_BUCKETS 256
#define FP_SCALE  67108864.0   // 2^26 fixed-point scale

// Fixed-point accumulation buckets + arrival counter.
// Zero-initialized at module load; the last CTA resets them each call,
// so every graph replay starts clean. Integer atomics commute exactly ->
// bit-identical output every call.
__device__ long long    g_buckets[N_BUCKETS];
__device__ unsigned int g_count;

__device__ __forceinline__ float warp_max(float v) {
    #pragma unroll
    for (int o = 16; o; o >>= 1) v = fmaxf(v, __shfl_xor_sync(0xffffffffu, v, o));
    return v;
}
__device__ __forceinline__ float warp_sum(float v) {
    #pragma unroll
    for (int o = 16; o; o >>= 1) v += __shfl_xor_sync(0xffffffffu, v, o);
    return v;
}
__device__ __forceinline__ long long warp_sum_ll(long long v) {
    #pragma unroll
    for (int o = 16; o; o >>= 1) v += __shfl_xor_sync(0xffffffffu, v, o);
    return v;
}

__global__ __launch_bounds__(BLK) void ebem_kernel(
    const float* __restrict__ x, const float* __restrict__ P,
    float* __restrict__ out)
{
    const int warp_in_blk = threadIdx.x >> 5;
    const int lane        = threadIdx.x & 31;
    const int row         = blockIdx.x * ROWS_PER_BLK + warp_in_blk;

    const float4* __restrict__ x4 = reinterpret_cast<const float4*>(x + (size_t)row * C);
    const float4* __restrict__ p4 = reinterpret_cast<const float4*>(P + (size_t)row * C);

    float4 xv[8], pv[8];
    #pragma unroll
    for (int i = 0; i < 8; i++) {
        const int idx = lane + 32 * i;
        if (idx < C4) {
            xv[i] = x4[idx];
            pv[i] = p4[idx];
        } else {
            xv[i] = make_float4(-1e30f, -1e30f, -1e30f, -1e30f);
            pv[i] = make_float4(0.f, 0.f, 0.f, 0.f);
        }
    }

    // row max (shuffle-only)
    float m = -1e30f;
    #pragma unroll
    for (int i = 0; i < 8; i++)
        m = fmaxf(m, fmaxf(fmaxf(xv[i].x, xv[i].y), fmaxf(xv[i].z, xv[i].w)));
    m = warp_max(m);

    // per-thread sums; padded lanes: exp(-1e30-m)=0, pv=0
    float se = 0.f, spx = 0.f, sp = 0.f;
    #pragma unroll
    for (int i = 0; i < 8; i++) {
        se  += __expf(xv[i].x - m) + __expf(xv[i].y - m)
             + __expf(xv[i].z - m) + __expf(xv[i].w - m);
        spx += pv[i].x * xv[i].x + pv[i].y * xv[i].y
             + pv[i].z * xv[i].z + pv[i].w * xv[i].w;
        sp  += pv[i].x + pv[i].y + pv[i].z + pv[i].w;
    }

    se  = warp_sum(se);
    spx = warp_sum(spx);
    sp  = warp_sum(sp);

    // CTA-level: 4 warp partials -> 1 fixed-point atomic + arrival
    __shared__ float s_part[ROWS_PER_BLK];
    __shared__ int   s_is_last;
    if (lane == 0) {
        float lse = m + logf(se);
        s_part[warp_in_blk] = spx - sp * lse;
    }
    __syncthreads();
    if (threadIdx.x == 0) {
        double acc = (double)s_part[0] + (double)s_part[1]
                   + (double)s_part[2] + (double)s_part[3];
        long long q = __double2ll_rn(acc * FP_SCALE);
        atomicAdd(reinterpret_cast<unsigned long long*>(
                      &g_buckets[blockIdx.x & (N_BUCKETS - 1)]),
                  (unsigned long long)q);
        __threadfence();
        unsigned int old = atomicAdd(&g_count, 1u);
        s_is_last = (old == GRID - 1u);
    }
    __syncthreads();

    // Last CTA: exact integer sum of buckets, write result, reset state.
    if (s_is_last) {
        __threadfence();   // acquire: bucket atomics precede counter arrivals
        volatile long long* vb = g_buckets;
        long long v = vb[threadIdx.x] + vb[threadIdx.x + BLK];

        v = warp_sum_ll(v);
        __shared__ long long sh[ROWS_PER_BLK];
        if (lane == 0) sh[warp_in_blk] = v;
        __syncthreads();
        if (warp_in_blk == 0) {
            long long t = (lane < ROWS_PER_BLK) ? sh[lane] : 0LL;
            #pragma unroll
            for (int o = 2; o; o >>= 1)
                t += __shfl_xor_sync(0xffffffffu, t, o);
            if (lane == 0) {
                out[0] = (float)(-((double)t / FP_SCALE) / (double)N_ROWS);
                g_count = 0u;
            }
        }
        // reset buckets for the next graph replay
        g_buckets[threadIdx.x]       = 0LL;
        g_buckets[threadIdx.x + BLK] = 0LL;
    }
}

extern "C" void kernel_launch(void* const* d_in, const int* in_sizes, int n_in,
                              void* d_out, int out_size)
{
    const float* x = (const float*)d_in[0];
    const float* P = (const float*)d_in[1];
    float* out = (float*)d_out;

    ebem_kernel<<<GRID, BLK>>>(x, P, out);
}